// round 3
// baseline (speedup 1.0000x reference)
#include <cuda_runtime.h>
#include <cstdint>

#define N_NODES 50000
#define N_EDGES 800000
#define FEAT    128
#define NUM_RELS 8
#define NSLOT   (NUM_RELS + 1)

// Scratch (allocation-free rule: __device__ globals)
__device__ float d_hw[(size_t)NSLOT * N_NODES * FEAT];   // 230.4 MB
__device__ float d_agg[(size_t)N_NODES * FEAT];          // 25.6 MB

// ---------------------------------------------------------------------------
// Phase 1: hw[r] = h @ W[r]   (fp32 SGEMM, 128x128 tile, BK=16, double buffer)
// ---------------------------------------------------------------------------
__global__ void __launch_bounds__(256, 1)
gemm_kernel(const float* __restrict__ h, const float* __restrict__ w) {
    const int r  = blockIdx.y;
    const int m0 = blockIdx.x * 128;
    const float* W   = w + (size_t)r * FEAT * FEAT;
    float*       out = d_hw + (size_t)r * N_NODES * FEAT;

    __shared__ float As[2][16][128];   // [buf][k][m]
    __shared__ float Bs[2][16][128];   // [buf][k][n]

    const int tid = threadIdx.x;
    const int tx  = tid & 15;          // output col group (8 cols each)
    const int ty  = tid >> 4;          // output row group (8 rows each)

    // A tile loads: 128 rows x 16 k = 512 float4; 2 per thread
    const int arow = tid >> 2;          // 0..63 (and +64)
    const int acol = (tid & 3) << 2;    // 0,4,8,12 (k within tile)
    // B tile loads: 16 k x 128 n = 512 float4; 2 per thread
    const int brow = tid >> 5;          // 0..7 (and +8)
    const int bcol = (tid & 31) << 2;   // 0..124

    float acc[8][8];
#pragma unroll
    for (int i = 0; i < 8; i++)
#pragma unroll
        for (int j = 0; j < 8; j++) acc[i][j] = 0.0f;

    // ---- prime stage 0 ----
#pragma unroll
    for (int i = 0; i < 2; i++) {
        int m = m0 + arow + i * 64;
        float4 v = make_float4(0.f, 0.f, 0.f, 0.f);
        if (m < N_NODES)
            v = *(const float4*)(h + (size_t)m * FEAT + acol);
        As[0][acol + 0][arow + i * 64] = v.x;
        As[0][acol + 1][arow + i * 64] = v.y;
        As[0][acol + 2][arow + i * 64] = v.z;
        As[0][acol + 3][arow + i * 64] = v.w;
    }
#pragma unroll
    for (int i = 0; i < 2; i++) {
        int k = brow + i * 8;
        *(float4*)&Bs[0][k][bcol] = *(const float4*)(W + k * FEAT + bcol);
    }
    __syncthreads();

#pragma unroll
    for (int kt = 0; kt < 8; kt++) {
        const int cur = kt & 1;
        const int nxt = cur ^ 1;
        if (kt < 7) {
            const int k0 = (kt + 1) * 16;
#pragma unroll
            for (int i = 0; i < 2; i++) {
                int m = m0 + arow + i * 64;
                float4 v = make_float4(0.f, 0.f, 0.f, 0.f);
                if (m < N_NODES)
                    v = *(const float4*)(h + (size_t)m * FEAT + k0 + acol);
                As[nxt][acol + 0][arow + i * 64] = v.x;
                As[nxt][acol + 1][arow + i * 64] = v.y;
                As[nxt][acol + 2][arow + i * 64] = v.z;
                As[nxt][acol + 3][arow + i * 64] = v.w;
            }
#pragma unroll
            for (int i = 0; i < 2; i++) {
                int k = brow + i * 8;
                *(float4*)&Bs[nxt][k][bcol] =
                    *(const float4*)(W + (k0 + k) * FEAT + bcol);
            }
        }
#pragma unroll
        for (int k = 0; k < 16; k++) {
            float4 a0 = *(const float4*)&As[cur][k][ty * 8];
            float4 a1 = *(const float4*)&As[cur][k][ty * 8 + 4];
            float4 b0 = *(const float4*)&Bs[cur][k][tx * 8];
            float4 b1 = *(const float4*)&Bs[cur][k][tx * 8 + 4];
            float am[8] = {a0.x, a0.y, a0.z, a0.w, a1.x, a1.y, a1.z, a1.w};
            float bn[8] = {b0.x, b0.y, b0.z, b0.w, b1.x, b1.y, b1.z, b1.w};
#pragma unroll
            for (int i = 0; i < 8; i++)
#pragma unroll
                for (int j = 0; j < 8; j++)
                    acc[i][j] = fmaf(am[i], bn[j], acc[i][j]);
        }
        __syncthreads();
    }

    // ---- store ----
#pragma unroll
    for (int i = 0; i < 8; i++) {
        int m = m0 + ty * 8 + i;
        if (m < N_NODES) {
            float4 s0 = make_float4(acc[i][0], acc[i][1], acc[i][2], acc[i][3]);
            float4 s1 = make_float4(acc[i][4], acc[i][5], acc[i][6], acc[i][7]);
            *(float4*)(out + (size_t)m * FEAT + tx * 8)     = s0;
            *(float4*)(out + (size_t)m * FEAT + tx * 8 + 4) = s1;
        }
    }
}

// ---------------------------------------------------------------------------
// Phase 2a: init agg to -inf sentinel
// ---------------------------------------------------------------------------
__global__ void init_agg_kernel() {
    const int idx = blockIdx.x * blockDim.x + threadIdx.x;
    const int total4 = N_NODES * FEAT / 4;
    if (idx >= total4) return;
    uint4 v;
    v.x = v.y = v.z = v.w = 0xFF800000u;  // -inf bits
    ((uint4*)d_agg)[idx] = v;
}

// ---------------------------------------------------------------------------
// Phase 2b: per-edge gather + scatter-max (1 warp / edge, float4 / lane)
// ---------------------------------------------------------------------------
__device__ __forceinline__ void atomicMaxF(float* addr, float v) {
    // Canonicalize -0.0 -> +0.0 so both zeros take the signed-int max branch.
    if (__float_as_uint(v) == 0x80000000u) v = 0.0f;
    if (v >= 0.0f)
        atomicMax((int*)addr, __float_as_int(v));
    else
        atomicMin((unsigned int*)addr, __float_as_uint(v));
}

__global__ void __launch_bounds__(256)
edge_kernel(const float* __restrict__ bias,
            const int* __restrict__ src,
            const int* __restrict__ dst,
            const int* __restrict__ rel) {
    const int gid  = blockIdx.x * blockDim.x + threadIdx.x;
    const int e    = gid >> 5;
    const int lane = gid & 31;
    if (e >= N_EDGES) return;

    const int s = __ldg(src + e);
    const int d = __ldg(dst + e);
    const int r = __ldg(rel + e);

    float4 v = *(const float4*)(d_hw + ((size_t)r * N_NODES + s) * FEAT + lane * 4);
    float4 b = __ldg((const float4*)(bias + (size_t)r * FEAT) + lane);

    float* a = d_agg + (size_t)d * FEAT + lane * 4;
    atomicMaxF(a + 0, v.x + b.x);
    atomicMaxF(a + 1, v.y + b.y);
    atomicMaxF(a + 2, v.z + b.z);
    atomicMaxF(a + 3, v.w + b.w);
}

// ---------------------------------------------------------------------------
// Phase 3: out = relu(hw[last] + agg' + bias[last]), agg'=-inf sentinel -> 0
// ---------------------------------------------------------------------------
__device__ __forceinline__ float dec_agg(float x) {
    return (__float_as_uint(x) == 0xFF800000u) ? 0.0f : x;
}

__global__ void __launch_bounds__(256)
finalize_kernel(const float* __restrict__ bias, float* __restrict__ out) {
    const int idx = blockIdx.x * blockDim.x + threadIdx.x;   // float4 index
    const int total4 = N_NODES * FEAT / 4;
    if (idx >= total4) return;
    const int o4 = idx & (FEAT / 4 - 1);  // float4 col within row

    const float4 hwv = ((const float4*)(d_hw + (size_t)NUM_RELS * N_NODES * FEAT))[idx];
    const float4 av  = ((const float4*)d_agg)[idx];
    const float4 bv  = __ldg((const float4*)(bias + (size_t)NUM_RELS * FEAT) + o4);

    float4 res;
    res.x = fmaxf(hwv.x + dec_agg(av.x) + bv.x, 0.0f);
    res.y = fmaxf(hwv.y + dec_agg(av.y) + bv.y, 0.0f);
    res.z = fmaxf(hwv.z + dec_agg(av.z) + bv.z, 0.0f);
    res.w = fmaxf(hwv.w + dec_agg(av.w) + bv.w, 0.0f);
    ((float4*)out)[idx] = res;
}

// ---------------------------------------------------------------------------
extern "C" void kernel_launch(void* const* d_in, const int* in_sizes, int n_in,
                              void* d_out, int out_size) {
    const float* h    = (const float*)d_in[0];
    const float* w    = (const float*)d_in[1];
    const float* bias = (const float*)d_in[2];
    const int*   src  = (const int*)d_in[3];
    const int*   dst  = (const int*)d_in[4];
    const int*   rel  = (const int*)d_in[5];
    float*       out  = (float*)d_out;

    const int m_tiles = (N_NODES + 127) / 128;         // 391
    gemm_kernel<<<dim3(m_tiles, NSLOT), 256>>>(h, w);

    const int agg4 = N_NODES * FEAT / 4;               // 1.6M
    init_agg_kernel<<<(agg4 + 255) / 256, 256>>>();

    const long long edge_threads = (long long)N_EDGES * 32;
    edge_kernel<<<(int)((edge_threads + 255) / 256), 256>>>(bias, src, dst, rel);

    finalize_kernel<<<(agg4 + 255) / 256, 256>>>(bias, out);
}

// round 4
// speedup vs baseline: 2.0271x; 2.0271x over previous
#include <cuda_runtime.h>
#include <cstdint>

#define N_NODES 50000
#define N_EDGES 800000
#define FEAT    128
#define NUM_RELS 8
#define NSLOT   (NUM_RELS + 1)

#define SCAN_BLK 512
#define NB_SCAN  ((N_NODES + SCAN_BLK - 1) / SCAN_BLK)   // 98

// Scratch (allocation-free rule: __device__ globals)
__device__ float d_hw[(size_t)NSLOT * N_NODES * FEAT];   // 230.4 MB (bias fused in)
__device__ int   d_cnt[N_NODES];
__device__ int   d_off[N_NODES];
__device__ int   d_cur[N_NODES];
__device__ int   d_blocksum[NB_SCAN];
__device__ int   d_rows[N_EDGES];                        // rel*N_NODES + src, binned by dst

// ---------------------------------------------------------------------------
// Phase 1: hwb[r] = h @ W[r] + b[r]  (fp32 SGEMM 128x128, BK=16, dbl buffer)
// ---------------------------------------------------------------------------
__global__ void __launch_bounds__(256)
gemm_kernel(const float* __restrict__ h, const float* __restrict__ w,
            const float* __restrict__ bias) {
    const int r  = blockIdx.y;
    const int m0 = blockIdx.x * 128;
    const float* W   = w + (size_t)r * FEAT * FEAT;
    float*       out = d_hw + (size_t)r * N_NODES * FEAT;

    __shared__ float As[2][16][128];   // [buf][k][m]
    __shared__ float Bs[2][16][128];   // [buf][k][n]

    const int tid = threadIdx.x;
    const int tx  = tid & 15;          // output col group (8 cols each)
    const int ty  = tid >> 4;          // output row group (8 rows each)

    const int arow = tid >> 2;          // 0..63 (and +64)
    const int acol = (tid & 3) << 2;    // k within tile: 0,4,8,12
    const int brow = tid >> 5;          // 0..7 (and +8)
    const int bcol = (tid & 31) << 2;   // 0..124

    float acc[8][8];
#pragma unroll
    for (int i = 0; i < 8; i++)
#pragma unroll
        for (int j = 0; j < 8; j++) acc[i][j] = 0.0f;

    // ---- prime stage 0 ----
#pragma unroll
    for (int i = 0; i < 2; i++) {
        int m = m0 + arow + i * 64;
        float4 v = make_float4(0.f, 0.f, 0.f, 0.f);
        if (m < N_NODES)
            v = *(const float4*)(h + (size_t)m * FEAT + acol);
        As[0][acol + 0][arow + i * 64] = v.x;
        As[0][acol + 1][arow + i * 64] = v.y;
        As[0][acol + 2][arow + i * 64] = v.z;
        As[0][acol + 3][arow + i * 64] = v.w;
    }
#pragma unroll
    for (int i = 0; i < 2; i++) {
        int k = brow + i * 8;
        *(float4*)&Bs[0][k][bcol] = *(const float4*)(W + k * FEAT + bcol);
    }
    __syncthreads();

#pragma unroll
    for (int kt = 0; kt < 8; kt++) {
        const int cur = kt & 1;
        const int nxt = cur ^ 1;
        if (kt < 7) {
            const int k0 = (kt + 1) * 16;
#pragma unroll
            for (int i = 0; i < 2; i++) {
                int m = m0 + arow + i * 64;
                float4 v = make_float4(0.f, 0.f, 0.f, 0.f);
                if (m < N_NODES)
                    v = *(const float4*)(h + (size_t)m * FEAT + k0 + acol);
                As[nxt][acol + 0][arow + i * 64] = v.x;
                As[nxt][acol + 1][arow + i * 64] = v.y;
                As[nxt][acol + 2][arow + i * 64] = v.z;
                As[nxt][acol + 3][arow + i * 64] = v.w;
            }
#pragma unroll
            for (int i = 0; i < 2; i++) {
                int k = brow + i * 8;
                *(float4*)&Bs[nxt][k][bcol] =
                    *(const float4*)(W + (k0 + k) * FEAT + bcol);
            }
        }
#pragma unroll
        for (int k = 0; k < 16; k++) {
            float4 a0 = *(const float4*)&As[cur][k][ty * 8];
            float4 a1 = *(const float4*)&As[cur][k][ty * 8 + 4];
            float4 b0 = *(const float4*)&Bs[cur][k][tx * 8];
            float4 b1 = *(const float4*)&Bs[cur][k][tx * 8 + 4];
            float am[8] = {a0.x, a0.y, a0.z, a0.w, a1.x, a1.y, a1.z, a1.w};
            float bn[8] = {b0.x, b0.y, b0.z, b0.w, b1.x, b1.y, b1.z, b1.w};
#pragma unroll
            for (int i = 0; i < 8; i++)
#pragma unroll
                for (int j = 0; j < 8; j++)
                    acc[i][j] = fmaf(am[i], bn[j], acc[i][j]);
        }
        __syncthreads();
    }

    // ---- store (+ fused bias) ----
    float bv[8];
#pragma unroll
    for (int j = 0; j < 8; j++)
        bv[j] = __ldg(bias + (size_t)r * FEAT + tx * 8 + j);

#pragma unroll
    for (int i = 0; i < 8; i++) {
        int m = m0 + ty * 8 + i;
        if (m < N_NODES) {
            float4 s0 = make_float4(acc[i][0] + bv[0], acc[i][1] + bv[1],
                                    acc[i][2] + bv[2], acc[i][3] + bv[3]);
            float4 s1 = make_float4(acc[i][4] + bv[4], acc[i][5] + bv[5],
                                    acc[i][6] + bv[6], acc[i][7] + bv[7]);
            *(float4*)(out + (size_t)m * FEAT + tx * 8)     = s0;
            *(float4*)(out + (size_t)m * FEAT + tx * 8 + 4) = s1;
        }
    }
}

// ---------------------------------------------------------------------------
// CSR build: count -> scan -> scatter
// ---------------------------------------------------------------------------
__global__ void zero_cnt_kernel() {
    int g = blockIdx.x * blockDim.x + threadIdx.x;
    if (g < N_NODES) d_cnt[g] = 0;
}

__global__ void count_kernel(const int* __restrict__ dst) {
    int e = blockIdx.x * blockDim.x + threadIdx.x;
    if (e < N_EDGES) atomicAdd(&d_cnt[__ldg(dst + e)], 1);
}

__global__ void __launch_bounds__(SCAN_BLK)
scan1_kernel() {
    __shared__ int s[SCAN_BLK];
    const int t = threadIdx.x;
    const int g = blockIdx.x * SCAN_BLK + t;
    int v = (g < N_NODES) ? d_cnt[g] : 0;
    s[t] = v;
    __syncthreads();
#pragma unroll
    for (int ofs = 1; ofs < SCAN_BLK; ofs <<= 1) {
        int add = (t >= ofs) ? s[t - ofs] : 0;
        __syncthreads();
        s[t] += add;
        __syncthreads();
    }
    if (g < N_NODES) d_off[g] = s[t] - v;           // exclusive
    if (t == SCAN_BLK - 1) d_blocksum[blockIdx.x] = s[t];
}

__global__ void scan2_kernel() {
    if (threadIdx.x == 0 && blockIdx.x == 0) {
        int acc = 0;
        for (int i = 0; i < NB_SCAN; i++) {
            int t = d_blocksum[i];
            d_blocksum[i] = acc;
            acc += t;
        }
    }
}

__global__ void scan3_kernel() {
    int g = blockIdx.x * blockDim.x + threadIdx.x;
    if (g < N_NODES) {
        int o = d_off[g] + d_blocksum[g / SCAN_BLK];
        d_off[g] = o;
        d_cur[g] = o;
    }
}

__global__ void scatter_kernel(const int* __restrict__ src,
                               const int* __restrict__ dst,
                               const int* __restrict__ rel) {
    int e = blockIdx.x * blockDim.x + threadIdx.x;
    if (e >= N_EDGES) return;
    int d   = __ldg(dst + e);
    int pos = atomicAdd(&d_cur[d], 1);
    d_rows[pos] = __ldg(rel + e) * N_NODES + __ldg(src + e);
}

// ---------------------------------------------------------------------------
// Aggregation + finalize: warp per dst node, register max-reduce, fused ReLU
// out = relu(hwb[8][n] + (deg>0 ? max_e(hwb[rel][src]) : 0))
// ---------------------------------------------------------------------------
__global__ void __launch_bounds__(256)
agg_finalize_kernel(float* __restrict__ out) {
    const int gid  = blockIdx.x * blockDim.x + threadIdx.x;
    const int nid  = gid >> 5;
    const int lane = gid & 31;
    if (nid >= N_NODES) return;

    const int deg = d_cnt[nid];
    const int off = d_off[nid];

    const float NEG = __int_as_float(0xFF800000);
    float4 acc = make_float4(NEG, NEG, NEG, NEG);

    int i = 0;
    for (; i + 2 <= deg; i += 2) {
        const int r0 = __ldg(&d_rows[off + i]);
        const int r1 = __ldg(&d_rows[off + i + 1]);
        const float4 v0 = *(const float4*)(d_hw + (size_t)r0 * FEAT + lane * 4);
        const float4 v1 = *(const float4*)(d_hw + (size_t)r1 * FEAT + lane * 4);
        acc.x = fmaxf(acc.x, fmaxf(v0.x, v1.x));
        acc.y = fmaxf(acc.y, fmaxf(v0.y, v1.y));
        acc.z = fmaxf(acc.z, fmaxf(v0.z, v1.z));
        acc.w = fmaxf(acc.w, fmaxf(v0.w, v1.w));
    }
    if (i < deg) {
        const int r0 = __ldg(&d_rows[off + i]);
        const float4 v0 = *(const float4*)(d_hw + (size_t)r0 * FEAT + lane * 4);
        acc.x = fmaxf(acc.x, v0.x);
        acc.y = fmaxf(acc.y, v0.y);
        acc.z = fmaxf(acc.z, v0.z);
        acc.w = fmaxf(acc.w, v0.w);
    }
    if (deg == 0) acc = make_float4(0.f, 0.f, 0.f, 0.f);

    const float4 self =
        *(const float4*)(d_hw + ((size_t)NUM_RELS * N_NODES + nid) * FEAT + lane * 4);

    float4 res;
    res.x = fmaxf(self.x + acc.x, 0.0f);
    res.y = fmaxf(self.y + acc.y, 0.0f);
    res.z = fmaxf(self.z + acc.z, 0.0f);
    res.w = fmaxf(self.w + acc.w, 0.0f);
    *(float4*)(out + (size_t)nid * FEAT + lane * 4) = res;
}

// ---------------------------------------------------------------------------
extern "C" void kernel_launch(void* const* d_in, const int* in_sizes, int n_in,
                              void* d_out, int out_size) {
    const float* h    = (const float*)d_in[0];
    const float* w    = (const float*)d_in[1];
    const float* bias = (const float*)d_in[2];
    const int*   src  = (const int*)d_in[3];
    const int*   dst  = (const int*)d_in[4];
    const int*   rel  = (const int*)d_in[5];
    float*       out  = (float*)d_out;

    const int m_tiles = (N_NODES + 127) / 128;         // 391
    gemm_kernel<<<dim3(m_tiles, NSLOT), 256>>>(h, w, bias);

    zero_cnt_kernel<<<(N_NODES + 255) / 256, 256>>>();
    count_kernel<<<(N_EDGES + 255) / 256, 256>>>(dst);
    scan1_kernel<<<NB_SCAN, SCAN_BLK>>>();
    scan2_kernel<<<1, 32>>>();
    scan3_kernel<<<(N_NODES + 255) / 256, 256>>>();
    scatter_kernel<<<(N_EDGES + 255) / 256, 256>>>(src, dst, rel);

    const long long agg_threads = (long long)N_NODES * 32;
    agg_finalize_kernel<<<(int)((agg_threads + 255) / 256), 256>>>(out);
}

// round 6
// speedup vs baseline: 3.7686x; 1.8591x over previous
#include <cuda_runtime.h>
#include <cuda_bf16.h>
#include <cstdint>

#define N_NODES 50000
#define N_EDGES 800000
#define FEAT    128
#define NUM_RELS 8
#define NSLOT   (NUM_RELS + 1)
#define M_TILES ((N_NODES + 127) / 128)   // 391

#define SCAN_BLK 512
#define NB_SCAN  ((N_NODES + SCAN_BLK - 1) / SCAN_BLK)   // 98

// ---------------- scratch (__device__ globals; allocation-free rule) -------
__device__ float d_hw[(size_t)NSLOT * N_NODES * FEAT];   // 230.4 MB (bias fused)
__device__ __nv_bfloat16 d_wth[(size_t)NSLOT * FEAT * FEAT];  // W^T hi [r][out][in]
__device__ __nv_bfloat16 d_wtl[(size_t)NSLOT * FEAT * FEAT];  // W^T lo
__device__ int d_cnt[N_NODES];
__device__ int d_off[N_NODES];
__device__ int d_cur[N_NODES];
__device__ int d_blocksum[NB_SCAN];
__device__ int d_rows[N_EDGES];                          // rel*N_NODES+src, binned by dst

// ---------------------------------------------------------------------------
// W prepass: transpose + fp32 -> bf16 hi/lo split. d_wt*[r][out][in]
// ---------------------------------------------------------------------------
__global__ void convert_w_kernel(const float* __restrict__ w) {
    int idx = blockIdx.x * blockDim.x + threadIdx.x;
    if (idx >= NSLOT * FEAT * FEAT) return;
    int r   = idx / (FEAT * FEAT);
    int rem = idx - r * (FEAT * FEAT);
    int n   = rem >> 7;          // out dim
    int k   = rem & 127;         // in dim
    float v = __ldg(w + (size_t)r * FEAT * FEAT + (size_t)k * FEAT + n);
    __nv_bfloat16 hi = __float2bfloat16(v);
    float lo = v - __bfloat162float(hi);
    d_wth[idx] = hi;
    d_wtl[idx] = __float2bfloat16(lo);
}

// ---------------------------------------------------------------------------
// Phase 1: hwb[r] = h @ W[r] + b[r] via mma.sync m16n8k16 bf16 split (3-pass)
// ---------------------------------------------------------------------------
#define LDK 136                           // padded row stride in bf16 elems
#define TILE_BYTES (128 * LDK * 2)        // 34816
#define SM_A_HI 0
#define SM_A_LO TILE_BYTES
#define SM_B_HI (2 * TILE_BYTES)
#define SM_B_LO (3 * TILE_BYTES)
#define SMEM_BYTES (4 * TILE_BYTES)       // 139264

__device__ __forceinline__ void mma16816(float* c, const uint32_t* a, const uint32_t* b) {
    asm volatile(
        "mma.sync.aligned.m16n8k16.row.col.f32.bf16.bf16.f32 "
        "{%0,%1,%2,%3}, {%4,%5,%6,%7}, {%8,%9}, {%0,%1,%2,%3};"
        : "+f"(c[0]), "+f"(c[1]), "+f"(c[2]), "+f"(c[3])
        : "r"(a[0]), "r"(a[1]), "r"(a[2]), "r"(a[3]), "r"(b[0]), "r"(b[1]));
}

__global__ void __launch_bounds__(256, 1)
gemm_mma_kernel(const float* __restrict__ h, const float* __restrict__ bias) {
    extern __shared__ char smem[];
    __nv_bfloat16* As_hi = (__nv_bfloat16*)(smem + SM_A_HI);
    __nv_bfloat16* As_lo = (__nv_bfloat16*)(smem + SM_A_LO);
    __nv_bfloat16* Bs_hi = (__nv_bfloat16*)(smem + SM_B_HI);
    __nv_bfloat16* Bs_lo = (__nv_bfloat16*)(smem + SM_B_LO);

    const int r    = blockIdx.x;
    const int m0   = blockIdx.y * 128;
    const int tid  = threadIdx.x;
    const int wid  = tid >> 5;
    const int lane = tid & 31;
    const int g    = lane >> 2;          // group id 0..7
    const int t    = lane & 3;           // thread-in-group 0..3

    // ---- A: load fp32 h, split hi/lo, store padded row-major ----
    // 128 rows x 32 float4 cols = 4096 chunks / 256 thr = 16 iters
#pragma unroll
    for (int it = 0; it < 16; it++) {
        int c    = it * 256 + tid;
        int row  = c >> 5;
        int col4 = (c & 31) << 2;
        int m    = m0 + row;
        float4 v = make_float4(0.f, 0.f, 0.f, 0.f);
        if (m < N_NODES) v = *(const float4*)(h + (size_t)m * FEAT + col4);

        __nv_bfloat162 h01 = __floats2bfloat162_rn(v.x, v.y);
        __nv_bfloat162 h23 = __floats2bfloat162_rn(v.z, v.w);
        float lx = v.x - __bfloat162float(h01.x);
        float ly = v.y - __bfloat162float(h01.y);
        float lz = v.z - __bfloat162float(h23.x);
        float lw = v.w - __bfloat162float(h23.y);
        __nv_bfloat162 l01 = __floats2bfloat162_rn(lx, ly);
        __nv_bfloat162 l23 = __floats2bfloat162_rn(lz, lw);

        int o = row * LDK + col4;
        *(uint2*)(As_hi + o) = make_uint2(*(uint32_t*)&h01, *(uint32_t*)&h23);
        *(uint2*)(As_lo + o) = make_uint2(*(uint32_t*)&l01, *(uint32_t*)&l23);
    }

    // ---- B: W^T hi/lo bf16 rows [n][k], uint4 = 8 bf16 per chunk ----
    const __nv_bfloat16* bh = d_wth + (size_t)r * FEAT * FEAT;
    const __nv_bfloat16* bl = d_wtl + (size_t)r * FEAT * FEAT;
#pragma unroll
    for (int it = 0; it < 8; it++) {
        int c    = it * 256 + tid;
        int row  = c >> 4;
        int col8 = (c & 15) << 3;
        int o = row * LDK + col8;
        *(uint4*)(Bs_hi + o) = *(const uint4*)(bh + (size_t)row * FEAT + col8);
        *(uint4*)(Bs_lo + o) = *(const uint4*)(bl + (size_t)row * FEAT + col8);
    }
    __syncthreads();

    // ---- warp tiling: 2 (m) x 4 (n); warp tile 64x32 ----
    const int wm = (wid >> 2) * 64;
    const int wn = (wid & 3) * 32;

    float acc[4][4][4];
#pragma unroll
    for (int i = 0; i < 4; i++)
#pragma unroll
        for (int j = 0; j < 4; j++)
#pragma unroll
            for (int q = 0; q < 4; q++) acc[i][j][q] = 0.0f;

#pragma unroll
    for (int ks = 0; ks < 8; ks++) {
        const int k0 = ks * 16;
        const int kc = k0 + 2 * t;       // fragment k column (bf16 index)

        uint32_t ah[4][4], al[4][4];
#pragma unroll
        for (int mf = 0; mf < 4; mf++) {
            int r0 = (wm + mf * 16 + g) * LDK;
            int r1 = r0 + 8 * LDK;
            ah[mf][0] = *(const uint32_t*)(As_hi + r0 + kc);
            ah[mf][1] = *(const uint32_t*)(As_hi + r1 + kc);
            ah[mf][2] = *(const uint32_t*)(As_hi + r0 + kc + 8);
            ah[mf][3] = *(const uint32_t*)(As_hi + r1 + kc + 8);
            al[mf][0] = *(const uint32_t*)(As_lo + r0 + kc);
            al[mf][1] = *(const uint32_t*)(As_lo + r1 + kc);
            al[mf][2] = *(const uint32_t*)(As_lo + r0 + kc + 8);
            al[mf][3] = *(const uint32_t*)(As_lo + r1 + kc + 8);
        }
        uint32_t bhf[4][2], blf[4][2];
#pragma unroll
        for (int nf = 0; nf < 4; nf++) {
            int nr = (wn + nf * 8 + g) * LDK;
            bhf[nf][0] = *(const uint32_t*)(Bs_hi + nr + kc);
            bhf[nf][1] = *(const uint32_t*)(Bs_hi + nr + kc + 8);
            blf[nf][0] = *(const uint32_t*)(Bs_lo + nr + kc);
            blf[nf][1] = *(const uint32_t*)(Bs_lo + nr + kc + 8);
        }
#pragma unroll
        for (int mf = 0; mf < 4; mf++)
#pragma unroll
            for (int nf = 0; nf < 4; nf++) {
                mma16816(acc[mf][nf], ah[mf], bhf[nf]);
                mma16816(acc[mf][nf], ah[mf], blf[nf]);
                mma16816(acc[mf][nf], al[mf], bhf[nf]);
            }
    }

    // ---- epilogue: + bias, store fp32 to d_hw ----
    float* outr = d_hw + (size_t)r * N_NODES * FEAT;
#pragma unroll
    for (int nf = 0; nf < 4; nf++) {
        const int n0 = wn + nf * 8 + 2 * t;
        const float2 bv = __ldg((const float2*)(bias + (size_t)r * FEAT + n0));
#pragma unroll
        for (int mf = 0; mf < 4; mf++) {
            int mrow0 = m0 + wm + mf * 16 + g;
            int mrow1 = mrow0 + 8;
            if (mrow0 < N_NODES) {
                float2 s = make_float2(acc[mf][nf][0] + bv.x, acc[mf][nf][1] + bv.y);
                *(float2*)(outr + (size_t)mrow0 * FEAT + n0) = s;
            }
            if (mrow1 < N_NODES) {
                float2 s = make_float2(acc[mf][nf][2] + bv.x, acc[mf][nf][3] + bv.y);
                *(float2*)(outr + (size_t)mrow1 * FEAT + n0) = s;
            }
        }
    }
}

// ---------------------------------------------------------------------------
// CSR build: count -> scan -> scatter  (unchanged)
// ---------------------------------------------------------------------------
__global__ void zero_cnt_kernel() {
    int g = blockIdx.x * blockDim.x + threadIdx.x;
    if (g < N_NODES) d_cnt[g] = 0;
}
__global__ void count_kernel(const int* __restrict__ dst) {
    int e = blockIdx.x * blockDim.x + threadIdx.x;
    if (e < N_EDGES) atomicAdd(&d_cnt[__ldg(dst + e)], 1);
}
__global__ void __launch_bounds__(SCAN_BLK)
scan1_kernel() {
    __shared__ int s[SCAN_BLK];
    const int t = threadIdx.x;
    const int g = blockIdx.x * SCAN_BLK + t;
    int v = (g < N_NODES) ? d_cnt[g] : 0;
    s[t] = v;
    __syncthreads();
#pragma unroll
    for (int ofs = 1; ofs < SCAN_BLK; ofs <<= 1) {
        int add = (t >= ofs) ? s[t - ofs] : 0;
        __syncthreads();
        s[t] += add;
        __syncthreads();
    }
    if (g < N_NODES) d_off[g] = s[t] - v;
    if (t == SCAN_BLK - 1) d_blocksum[blockIdx.x] = s[t];
}
__global__ void scan2_kernel() {
    if (threadIdx.x == 0 && blockIdx.x == 0) {
        int acc = 0;
        for (int i = 0; i < NB_SCAN; i++) { int t = d_blocksum[i]; d_blocksum[i] = acc; acc += t; }
    }
}
__global__ void scan3_kernel() {
    int g = blockIdx.x * blockDim.x + threadIdx.x;
    if (g < N_NODES) {
        int o = d_off[g] + d_blocksum[g / SCAN_BLK];
        d_off[g] = o;
        d_cur[g] = o;
    }
}
__global__ void scatter_kernel(const int* __restrict__ src,
                               const int* __restrict__ dst,
                               const int* __restrict__ rel) {
    int e = blockIdx.x * blockDim.x + threadIdx.x;
    if (e >= N_EDGES) return;
    int d = __ldg(dst + e);
    int pos = atomicAdd(&d_cur[d], 1);
    d_rows[pos] = __ldg(rel + e) * N_NODES + __ldg(src + e);
}

// ---------------------------------------------------------------------------
// Aggregation + finalize (unchanged)
// ---------------------------------------------------------------------------
__global__ void __launch_bounds__(256)
agg_finalize_kernel(float* __restrict__ out) {
    const int gid  = blockIdx.x * blockDim.x + threadIdx.x;
    const int nid  = gid >> 5;
    const int lane = gid & 31;
    if (nid >= N_NODES) return;

    const int deg = d_cnt[nid];
    const int off = d_off[nid];

    const float NEG = __int_as_float(0xFF800000);
    float4 acc = make_float4(NEG, NEG, NEG, NEG);

    int i = 0;
    for (; i + 2 <= deg; i += 2) {
        const int r0 = __ldg(&d_rows[off + i]);
        const int r1 = __ldg(&d_rows[off + i + 1]);
        const float4 v0 = *(const float4*)(d_hw + (size_t)r0 * FEAT + lane * 4);
        const float4 v1 = *(const float4*)(d_hw + (size_t)r1 * FEAT + lane * 4);
        acc.x = fmaxf(acc.x, fmaxf(v0.x, v1.x));
        acc.y = fmaxf(acc.y, fmaxf(v0.y, v1.y));
        acc.z = fmaxf(acc.z, fmaxf(v0.z, v1.z));
        acc.w = fmaxf(acc.w, fmaxf(v0.w, v1.w));
    }
    if (i < deg) {
        const int r0 = __ldg(&d_rows[off + i]);
        const float4 v0 = *(const float4*)(d_hw + (size_t)r0 * FEAT + lane * 4);
        acc.x = fmaxf(acc.x, v0.x);
        acc.y = fmaxf(acc.y, v0.y);
        acc.z = fmaxf(acc.z, v0.z);
        acc.w = fmaxf(acc.w, v0.w);
    }
    if (deg == 0) acc = make_float4(0.f, 0.f, 0.f, 0.f);

    const float4 self =
        *(const float4*)(d_hw + ((size_t)NUM_RELS * N_NODES + nid) * FEAT + lane * 4);

    float4 res;
    res.x = fmaxf(self.x + acc.x, 0.0f);
    res.y = fmaxf(self.y + acc.y, 0.0f);
    res.z = fmaxf(self.z + acc.z, 0.0f);
    res.w = fmaxf(self.w + acc.w, 0.0f);
    *(float4*)(out + (size_t)nid * FEAT + lane * 4) = res;
}

// ---------------------------------------------------------------------------
extern "C" void kernel_launch(void* const* d_in, const int* in_sizes, int n_in,
                              void* d_out, int out_size) {
    const float* h    = (const float*)d_in[0];
    const float* w    = (const float*)d_in[1];
    const float* bias = (const float*)d_in[2];
    const int*   src  = (const int*)d_in[3];
    const int*   dst  = (const int*)d_in[4];
    const int*   rel  = (const int*)d_in[5];
    float*       out  = (float*)d_out;

    cudaFuncSetAttribute(gemm_mma_kernel,
                         cudaFuncAttributeMaxDynamicSharedMemorySize, SMEM_BYTES);

    const int wtot = NSLOT * FEAT * FEAT;
    convert_w_kernel<<<(wtot + 255) / 256, 256>>>(w);

    gemm_mma_kernel<<<dim3(NSLOT, M_TILES), 256, SMEM_BYTES>>>(h, bias);

    zero_cnt_kernel<<<(N_NODES + 255) / 256, 256>>>();
    count_kernel<<<(N_EDGES + 255) / 256, 256>>>(dst);
    scan1_kernel<<<NB_SCAN, SCAN_BLK>>>();
    scan2_kernel<<<1, 32>>>();
    scan3_kernel<<<(N_NODES + 255) / 256, 256>>>();
    scatter_kernel<<<(N_EDGES + 255) / 256, 256>>>(src, dst, rel);

    const long long agg_threads = (long long)N_NODES * 32;
    agg_finalize_kernel<<<(int)((agg_threads + 255) / 256), 256>>>(out);
}